// round 13
// baseline (speedup 1.0000x reference)
#include <cuda_runtime.h>
#include <cuda_bf16.h>
#include <cuda_fp16.h>
#include <stdint.h>
#include <math.h>

#define N_NODES 50000
#define N_EDGES 800000
#define IN_F    256
#define OUT_F   64
#define N_HEADS 8
#define HF      (N_HEADS * OUT_F)   // 512

// ---------------- device scratch ---------------------------------------------
__device__ __half g_hh[(size_t)N_NODES * HF];      // fp16 h for gather (~51 MB)
__device__ float g_aself[N_NODES * N_HEADS];
__device__ float g_aneigh[N_NODES * N_HEADS];
__device__ int   g_deg[N_NODES];
__device__ int   g_offs[N_NODES + 1];
__device__ int   g_cursor[N_NODES];
__device__ int   g_csr_src[N_EDGES];
__device__ float g_csr_m[N_EDGES];
// fp16 operands
__device__ __half g_xh[(size_t)N_NODES * IN_F];
__device__ __half g_wth[N_HEADS * OUT_F * IN_F];   // [hd][n][k]

// ---------------- operand prep (fp32 -> fp16), x and W merged ----------------
#define XPAIRS (N_NODES * IN_F / 2)
#define WELEMS (N_HEADS * OUT_F * IN_F)
__global__ void k_prep(const float* __restrict__ x, const float* __restrict__ W) {
    int i = blockIdx.x * blockDim.x + threadIdx.x;
    if (i < XPAIRS) {
        float2 v = ((const float2*)x)[i];
        ((__half2*)g_xh)[i] = __floats2half2_rn(v.x, v.y);
    } else {
        int j = i - XPAIRS;
        if (j < WELEMS) {
            int k  = j & (IN_F - 1);
            int n  = (j >> 8) & (OUT_F - 1);
            int hd = j >> 14;
            g_wth[j] = __float2half_rn(W[((size_t)hd * IN_F + k) * OUT_F + n]);
        }
    }
}

// ---------------- CSR build --------------------------------------------------
__global__ void k_zero_deg() {
    int i = blockIdx.x * blockDim.x + threadIdx.x;
    if (i < N_NODES) g_deg[i] = 0;
}

__global__ void k_count(const int* __restrict__ dst) {
    int e = blockIdx.x * blockDim.x + threadIdx.x;
    if (e < N_EDGES) atomicAdd(&g_deg[dst[e]], 1);
}

__global__ void k_scan() {
    __shared__ int warp_sums[32];
    int tid = threadIdx.x, lane = tid & 31, wid = tid >> 5;
    int carry = 0;
    for (int base = 0; base < N_NODES; base += 1024) {
        int i = base + tid;
        int v = (i < N_NODES) ? g_deg[i] : 0;
        int xsum = v;
#pragma unroll
        for (int o = 1; o < 32; o <<= 1) {
            int t = __shfl_up_sync(0xffffffffu, xsum, o);
            if (lane >= o) xsum += t;
        }
        if (lane == 31) warp_sums[wid] = xsum;
        __syncthreads();
        if (wid == 0) {
            int s = warp_sums[lane];
#pragma unroll
            for (int o = 1; o < 32; o <<= 1) {
                int t = __shfl_up_sync(0xffffffffu, s, o);
                if (lane >= o) s += t;
            }
            warp_sums[lane] = s;
        }
        __syncthreads();
        int woff = (wid == 0) ? 0 : warp_sums[wid - 1];
        int incl = xsum + woff;
        if (i < N_NODES) {
            int excl = carry + incl - v;
            g_offs[i]   = excl;
            g_cursor[i] = excl;
        }
        carry += warp_sums[31];
        __syncthreads();
    }
    if (tid == 0) g_offs[N_NODES] = carry;
}

// fill CSR: (src, m) only — 8 B/edge scattered
__global__ void k_fill(const int* __restrict__ src, const int* __restrict__ dst,
                       const float* __restrict__ M) {
    int e = blockIdx.x * blockDim.x + threadIdx.x;
    if (e >= N_EDGES) return;
    int d = dst[e];
    int p = atomicAdd(&g_cursor[d], 1);
    g_csr_src[p] = src[e];
    g_csr_m[p]   = M[e];
}

// ---------------- fp16 mma.sync GEMM, BM=256, cp.async 3-stage ---------------
#define MMA_F16(d, a0, a1, a2, a3, b0, b1)                                    \
    asm volatile(                                                             \
        "mma.sync.aligned.m16n8k16.row.col.f32.f16.f16.f32 "                  \
        "{%0,%1,%2,%3}, {%4,%5,%6,%7}, {%8,%9}, {%0,%1,%2,%3};"               \
        : "+f"(d[0]), "+f"(d[1]), "+f"(d[2]), "+f"(d[3])                      \
        : "r"(a0), "r"(a1), "r"(a2), "r"(a3), "r"(b0), "r"(b1))

#define LDSM_X4(r, addr)                                                      \
    asm volatile("ldmatrix.sync.aligned.m8n8.x4.shared.b16 {%0,%1,%2,%3}, [%4];" \
        : "=r"((r)[0]), "=r"((r)[1]), "=r"((r)[2]), "=r"((r)[3]) : "r"(addr))

#define CP16(dst, src, sz)                                                    \
    asm volatile("cp.async.cg.shared.global [%0], [%1], 16, %2;"              \
        :: "r"(dst), "l"(src), "r"(sz) : "memory")
#define CP_COMMIT() asm volatile("cp.async.commit_group;" ::: "memory")

// smem stage layout (bytes): rows padded to 20 words (80B)
#define OFF_A  0
#define OFF_B  20480          // 256 rows * 80B
#define STAGE  25600          // + 64 rows * 80B
#define GEMM_SMEM (3 * STAGE) // 76800
#define BM 256

__global__ void __launch_bounds__(256, 2) k_gemm(const float* __restrict__ a_vec,
                                                 int hbase) {
    extern __shared__ char smem[];
    const uint32_t sb = (uint32_t)__cvta_generic_to_shared(smem);

    const int tid  = threadIdx.x;
    const int w    = tid >> 5;
    const int lane = tid & 31;
    const int g    = lane >> 2;
    const int tig  = lane & 3;
    const int hd   = blockIdx.x + hbase;
    const int row0 = blockIdx.y * BM;

    float acc0[8][4], acc1[8][4];
#pragma unroll
    for (int j = 0; j < 8; j++)
#pragma unroll
        for (int i = 0; i < 4; i++) { acc0[j][i] = 0.f; acc1[j][i] = 0.f; }

    // ldmatrix per-lane base offsets (within a stage): warp covers rows w*32..w*32+31
    const int a_row  = w * 32 + (lane & 15);
    const int a_colw = (lane >> 4) * 4;
    const uint32_t aoff0 = OFF_A + (uint32_t)(a_row * 20 + a_colw) * 4;
    const uint32_t aoff1 = aoff0 + 16 * 80;      // +16 rows
    const int b_row  = (lane & 7) + ((lane >> 4) << 3);
    const int b_colw = ((lane >> 3) & 1) * 4;
    const uint32_t boff = OFF_B + (uint32_t)(b_row * 20 + b_colw) * 4;

    const uint4* x4 = (const uint4*)g_xh;        // 32 uint4 per x row
    const uint4* w4 = (const uint4*)g_wth;

    // per-thread cp.async assignments: A gets 4 uint4/thread, B 1/thread
    int   rA[4], szA[4];
    size_t srA[4];
    uint32_t dA[4];
    const int qA = tid & 3;
#pragma unroll
    for (int t = 0; t < 4; t++) {
        int i = tid + t * 256;
        rA[t] = i >> 2;
        int gr = row0 + rA[t];
        szA[t] = (gr < N_NODES) ? 16 : 0;
        srA[t] = (size_t)((gr < N_NODES) ? gr : 0) * 32;
        dA[t]  = (uint32_t)(rA[t] * 80 + qA * 16);
    }
    const int rB = tid >> 2, qB = tid & 3;
    const size_t srB = (size_t)(hd * 64 + rB) * 32;
    const uint32_t dB = (uint32_t)(rB * 80 + qB * 16);

#define ISSUE_TILE(st, kit)                                                   \
    do {                                                                      \
        const int kw = (kit) * 4;                                             \
        const uint32_t base = sb + (st) * STAGE;                              \
        CP16(base + OFF_A + dA[0], x4 + srA[0] + kw + qA, szA[0]);            \
        CP16(base + OFF_A + dA[1], x4 + srA[1] + kw + qA, szA[1]);            \
        CP16(base + OFF_A + dA[2], x4 + srA[2] + kw + qA, szA[2]);            \
        CP16(base + OFF_A + dA[3], x4 + srA[3] + kw + qA, szA[3]);            \
        CP16(base + OFF_B + dB,  w4 + srB + kw + qB, 16);                     \
        CP_COMMIT();                                                          \
    } while (0)

    ISSUE_TILE(0, 0);
    ISSUE_TILE(1, 1);

#pragma unroll
    for (int kit = 0; kit < 8; kit++) {
        const int st = kit % 3;
        if (kit + 2 < 8) {
            ISSUE_TILE((kit + 2) % 3, kit + 2);
            asm volatile("cp.async.wait_group 2;" ::: "memory");
        } else if (kit + 1 < 8) {
            asm volatile("cp.async.wait_group 1;" ::: "memory");
        } else {
            asm volatile("cp.async.wait_group 0;" ::: "memory");
        }
        __syncthreads();

        const uint32_t sbase = st * STAGE + sb;
#pragma unroll
        for (int kt = 0; kt < 2; kt++) {
            const uint32_t koff = kt * 32;       // 8 words
            uint32_t ar0[4], ar1[4];
            LDSM_X4(ar0, sbase + aoff0 + koff);
            LDSM_X4(ar1, sbase + aoff1 + koff);
#pragma unroll
            for (int q = 0; q < 4; q++) {
                const uint32_t qoff = q * 1280 + koff;   // 16 rows * 80B
                uint32_t br[4];
                LDSM_X4(br, sbase + boff + qoff);
                MMA_F16(acc0[2*q],   ar0[0], ar0[1], ar0[2], ar0[3], br[0], br[1]);
                MMA_F16(acc0[2*q+1], ar0[0], ar0[1], ar0[2], ar0[3], br[2], br[3]);
                MMA_F16(acc1[2*q],   ar1[0], ar1[1], ar1[2], ar1[3], br[0], br[1]);
                MMA_F16(acc1[2*q+1], ar1[0], ar1[1], ar1[2], ar1[3], br[2], br[3]);
            }
        }
        __syncthreads();
    }

    // ---- epilogue: fused attention dots + fp16 h store (two m16 blocks) ----
    const float* ac = a_vec + hd * 2 * OUT_F;
#pragma unroll
    for (int half = 0; half < 2; half++) {
        float (*acc)[4] = half ? acc1 : acc0;
        const int ra = row0 + w * 32 + half * 16 + g;
        float s0 = 0.f, s1 = 0.f, t0 = 0.f, t1 = 0.f;
#pragma unroll
        for (int j = 0; j < 8; j++) {
            int c = j * 8 + 2 * tig;
            float2 as = *(const float2*)(ac + c);
            float2 an = *(const float2*)(ac + OUT_F + c);
            s0 += acc[j][0] * as.x + acc[j][1] * as.y;
            s1 += acc[j][2] * as.x + acc[j][3] * as.y;
            t0 += acc[j][0] * an.x + acc[j][1] * an.y;
            t1 += acc[j][2] * an.x + acc[j][3] * an.y;
        }
#pragma unroll
        for (int o = 1; o < 4; o <<= 1) {
            s0 += __shfl_xor_sync(0xffffffffu, s0, o);
            s1 += __shfl_xor_sync(0xffffffffu, s1, o);
            t0 += __shfl_xor_sync(0xffffffffu, t0, o);
            t1 += __shfl_xor_sync(0xffffffffu, t1, o);
        }
        if (tig == 0) {
            if (ra < N_NODES) {
                g_aself[ra * N_HEADS + hd]  = s0;
                g_aneigh[ra * N_HEADS + hd] = t0;
            }
            if (ra + 8 < N_NODES) {
                g_aself[(ra + 8) * N_HEADS + hd]  = s1;
                g_aneigh[(ra + 8) * N_HEADS + hd] = t1;
            }
        }
        if (ra < N_NODES) {
            __half2* hp = (__half2*)(g_hh + (size_t)ra * HF + hd * OUT_F);
#pragma unroll
            for (int j = 0; j < 8; j++)
                hp[j * 4 + tig] = __floats2half2_rn(acc[j][0], acc[j][1]);
        }
        if (ra + 8 < N_NODES) {
            __half2* hp = (__half2*)(g_hh + (size_t)(ra + 8) * HF + hd * OUT_F);
#pragma unroll
            for (int j = 0; j < 8; j++)
                hp[j * 4 + tig] = __floats2half2_rn(acc[j][2], acc[j][3]);
        }
    }
}

// ---------------- aggregation: one warp per node, 4 heads (half) -------------
// lane covers 8 fp16 cols (1 uint4); head = hb*4 + (lane>>3)
__global__ void k_agg4(float* __restrict__ out, int hb) {
    int wid = threadIdx.x >> 5, lane = threadIdx.x & 31;
    int n = blockIdx.x * 8 + wid;
    if (n >= N_NODES) return;

    int s = g_offs[n], e = g_offs[n + 1];
    const uint4* hh4 = (const uint4*)g_hh;          // 64 uint4 per node row
    const int vi = hb * 32 + lane;                  // this lane's uint4
    const int hsel = hb * 4 + (lane >> 3);
    const float an = __ldg(&g_aneigh[n * 8 + hsel]);

    float acc[8];
#pragma unroll
    for (int j = 0; j < 8; j++) acc[j] = 0.f;
    float den = 0.f;

    int u0 = 0, u1 = 0;
    float m0 = 0.f, m1 = 0.f, as0 = 0.f;
    if (s < e) {
        u0 = __ldg(&g_csr_src[s]); m0 = __ldg(&g_csr_m[s]);
        as0 = __ldg(&g_aself[u0 * 8 + hsel]);
    }
    if (s + 1 < e) { u1 = __ldg(&g_csr_src[s + 1]); m1 = __ldg(&g_csr_m[s + 1]); }

    for (int i = s; i < e; i++) {
        const int   uc  = u0;
        const float mc  = m0;
        const float asc = as0;
        u0 = u1; m0 = m1;
        if (i + 1 < e) as0 = __ldg(&g_aself[u0 * 8 + hsel]);
        if (i + 2 < e) { u1 = __ldg(&g_csr_src[i + 2]); m1 = __ldg(&g_csr_m[i + 2]); }

        float ev = asc + an;
        ev = (ev > 0.f) ? ev : 0.2f * ev;           // leaky_relu
        float wgt = __expf(ev * mc);
        uint4 v = hh4[(size_t)uc * 64 + vi];
        den += wgt;
        const __half2* p = (const __half2*)&v;
#pragma unroll
        for (int j = 0; j < 4; j++) {
            float2 f = __half22float2(p[j]);
            acc[2*j]   = fmaf(wgt, f.x, acc[2*j]);
            acc[2*j+1] = fmaf(wgt, f.y, acc[2*j+1]);
        }
    }
    float inv = 1.f / (den + 1e-16f);
    float* op = out + (size_t)n * HF + hb * 256 + lane * 8;
#pragma unroll
    for (int j = 0; j < 8; j++) {
        float v = acc[j] * inv;
        acc[j] = (v > 0.f) ? v : expm1f(v);         // elu
    }
    *(float4*)(op)     = make_float4(acc[0], acc[1], acc[2], acc[3]);
    *(float4*)(op + 4) = make_float4(acc[4], acc[5], acc[6], acc[7]);
}

// ---------------- launch: 2-deep head-pipelined schedule ---------------------
extern "C" void kernel_launch(void* const* d_in, const int* in_sizes, int n_in,
                              void* d_out, int out_size) {
    const float* x   = (const float*)d_in[0];
    const int*   src = (const int*)d_in[1];
    const int*   dst = (const int*)d_in[2];
    const float* M   = (const float*)d_in[3];
    const float* W   = (const float*)d_in[4];
    const float* a   = (const float*)d_in[5];
    float* out = (float*)d_out;

    static cudaStream_t s2 = nullptr;
    static cudaEvent_t ev_fork = nullptr, ev_fill = nullptr,
                       ev_g1 = nullptr, ev_a1 = nullptr;
    if (!s2) {
        cudaStreamCreateWithFlags(&s2, cudaStreamNonBlocking);
        cudaEventCreateWithFlags(&ev_fork, cudaEventDisableTiming);
        cudaEventCreateWithFlags(&ev_fill, cudaEventDisableTiming);
        cudaEventCreateWithFlags(&ev_g1,   cudaEventDisableTiming);
        cudaEventCreateWithFlags(&ev_a1,   cudaEventDisableTiming);
        cudaFuncSetAttribute(k_gemm, cudaFuncAttributeMaxDynamicSharedMemorySize,
                             GEMM_SMEM);
    }

    const int NB = (N_NODES + BM - 1) / BM;

    // fork chain B (s2): CSR build
    cudaEventRecord(ev_fork, 0);
    cudaStreamWaitEvent(s2, ev_fork, 0);
    k_zero_deg<<<(N_NODES + 255) / 256, 256, 0, s2>>>();
    k_count<<<(N_EDGES + 255) / 256, 256, 0, s2>>>(dst);
    k_scan<<<1, 1024, 0, s2>>>();
    k_fill<<<(N_EDGES + 255) / 256, 256, 0, s2>>>(src, dst, M);
    cudaEventRecord(ev_fill, s2);

    // chain A (stream 0): prep -> gemm half 1 -> gemm half 2
    k_prep<<<(XPAIRS + WELEMS + 255) / 256, 256>>>(x, W);
    k_gemm<<<dim3(4, NB), 256, GEMM_SMEM>>>(a, 0);
    cudaEventRecord(ev_g1, 0);
    k_gemm<<<dim3(4, NB), 256, GEMM_SMEM>>>(a, 4);

    // agg half 1 on s2 (after fill [stream order] + gemm half 1), overlaps gemm half 2
    cudaStreamWaitEvent(s2, ev_g1, 0);
    k_agg4<<<(N_NODES + 7) / 8, 256, 0, s2>>>(out, 0);
    cudaEventRecord(ev_a1, s2);

    // agg half 2 on stream 0 (after gemm half 2 [stream order] + fill)
    cudaStreamWaitEvent(0, ev_fill, 0);
    k_agg4<<<(N_NODES + 7) / 8, 256>>>(out, 1);

    // join
    cudaStreamWaitEvent(0, ev_a1, 0);
}

// round 14
// speedup vs baseline: 1.1131x; 1.1131x over previous
#include <cuda_runtime.h>
#include <cuda_bf16.h>
#include <cuda_fp16.h>
#include <stdint.h>
#include <math.h>

#define N_NODES 50000
#define N_EDGES 800000
#define IN_F    256
#define OUT_F   64
#define N_HEADS 8
#define HF      (N_HEADS * OUT_F)   // 512

// ---------------- device scratch ---------------------------------------------
__device__ __half g_hh[(size_t)N_NODES * HF];      // fp16 h for gather (~51 MB)
__device__ float g_aself[N_NODES * N_HEADS];
__device__ float g_aneigh[N_NODES * N_HEADS];
__device__ int   g_deg[N_NODES];
__device__ int   g_offs[N_NODES + 1];
__device__ int   g_cursor[N_NODES];
__device__ int   g_csr_src[N_EDGES];
__device__ float g_csr_m[N_EDGES];
// fp16 operands
__device__ __half g_xh[(size_t)N_NODES * IN_F];
__device__ __half g_wth[N_HEADS * OUT_F * IN_F];   // [hd][n][k]

// ---------------- operand prep (fp32 -> fp16), x and W merged ----------------
#define XPAIRS (N_NODES * IN_F / 2)
#define WELEMS (N_HEADS * OUT_F * IN_F)
__global__ void k_prep(const float* __restrict__ x, const float* __restrict__ W) {
    int i = blockIdx.x * blockDim.x + threadIdx.x;
    if (i < XPAIRS) {
        float2 v = ((const float2*)x)[i];
        ((__half2*)g_xh)[i] = __floats2half2_rn(v.x, v.y);
    } else {
        int j = i - XPAIRS;
        if (j < WELEMS) {
            int k  = j & (IN_F - 1);
            int n  = (j >> 8) & (OUT_F - 1);
            int hd = j >> 14;
            g_wth[j] = __float2half_rn(W[((size_t)hd * IN_F + k) * OUT_F + n]);
        }
    }
}

// ---------------- CSR build --------------------------------------------------
__global__ void k_zero_deg() {
    int i = blockIdx.x * blockDim.x + threadIdx.x;
    if (i < N_NODES) g_deg[i] = 0;
}

__global__ void k_count(const int* __restrict__ dst) {
    int e = blockIdx.x * blockDim.x + threadIdx.x;
    if (e < N_EDGES) atomicAdd(&g_deg[dst[e]], 1);
}

__global__ void k_scan() {
    __shared__ int warp_sums[32];
    int tid = threadIdx.x, lane = tid & 31, wid = tid >> 5;
    int carry = 0;
    for (int base = 0; base < N_NODES; base += 1024) {
        int i = base + tid;
        int v = (i < N_NODES) ? g_deg[i] : 0;
        int xsum = v;
#pragma unroll
        for (int o = 1; o < 32; o <<= 1) {
            int t = __shfl_up_sync(0xffffffffu, xsum, o);
            if (lane >= o) xsum += t;
        }
        if (lane == 31) warp_sums[wid] = xsum;
        __syncthreads();
        if (wid == 0) {
            int s = warp_sums[lane];
#pragma unroll
            for (int o = 1; o < 32; o <<= 1) {
                int t = __shfl_up_sync(0xffffffffu, s, o);
                if (lane >= o) s += t;
            }
            warp_sums[lane] = s;
        }
        __syncthreads();
        int woff = (wid == 0) ? 0 : warp_sums[wid - 1];
        int incl = xsum + woff;
        if (i < N_NODES) {
            int excl = carry + incl - v;
            g_offs[i]   = excl;
            g_cursor[i] = excl;
        }
        carry += warp_sums[31];
        __syncthreads();
    }
    if (tid == 0) g_offs[N_NODES] = carry;
}

// fill CSR: (src, m) only — 8 B/edge scattered
__global__ void k_fill(const int* __restrict__ src, const int* __restrict__ dst,
                       const float* __restrict__ M) {
    int e = blockIdx.x * blockDim.x + threadIdx.x;
    if (e >= N_EDGES) return;
    int d = dst[e];
    int p = atomicAdd(&g_cursor[d], 1);
    g_csr_src[p] = src[e];
    g_csr_m[p]   = M[e];
}

// ---------------- fp16 mma.sync GEMM, BM=256, 3-stage, single-sync -----------
#define MMA_F16(d, a0, a1, a2, a3, b0, b1)                                    \
    asm volatile(                                                             \
        "mma.sync.aligned.m16n8k16.row.col.f32.f16.f16.f32 "                  \
        "{%0,%1,%2,%3}, {%4,%5,%6,%7}, {%8,%9}, {%0,%1,%2,%3};"               \
        : "+f"(d[0]), "+f"(d[1]), "+f"(d[2]), "+f"(d[3])                      \
        : "r"(a0), "r"(a1), "r"(a2), "r"(a3), "r"(b0), "r"(b1))

#define LDSM_X4(r, addr)                                                      \
    asm volatile("ldmatrix.sync.aligned.m8n8.x4.shared.b16 {%0,%1,%2,%3}, [%4];" \
        : "=r"((r)[0]), "=r"((r)[1]), "=r"((r)[2]), "=r"((r)[3]) : "r"(addr))

#define CP16(dst, src, sz)                                                    \
    asm volatile("cp.async.cg.shared.global [%0], [%1], 16, %2;"              \
        :: "r"(dst), "l"(src), "r"(sz) : "memory")
#define CP_COMMIT() asm volatile("cp.async.commit_group;" ::: "memory")

// smem stage layout (bytes): rows padded to 20 words (80B)
#define OFF_A  0
#define OFF_B  20480          // 256 rows * 80B
#define STAGE  25600          // + 64 rows * 80B
#define GEMM_SMEM (3 * STAGE) // 76800
#define BM 256

__global__ void __launch_bounds__(256, 2) k_gemm(const float* __restrict__ a_vec) {
    extern __shared__ char smem[];
    const uint32_t sb = (uint32_t)__cvta_generic_to_shared(smem);

    const int tid  = threadIdx.x;
    const int w    = tid >> 5;
    const int lane = tid & 31;
    const int g    = lane >> 2;
    const int tig  = lane & 3;
    const int hd   = blockIdx.x;                 // head fastest: L2 x reuse
    const int row0 = blockIdx.y * BM;

    float acc0[8][4], acc1[8][4];
#pragma unroll
    for (int j = 0; j < 8; j++)
#pragma unroll
        for (int i = 0; i < 4; i++) { acc0[j][i] = 0.f; acc1[j][i] = 0.f; }

    // ldmatrix per-lane base offsets (within a stage): warp covers rows w*32..w*32+31
    const int a_row  = w * 32 + (lane & 15);
    const int a_colw = (lane >> 4) * 4;
    const uint32_t aoff0 = OFF_A + (uint32_t)(a_row * 20 + a_colw) * 4;
    const uint32_t aoff1 = aoff0 + 16 * 80;      // +16 rows
    const int b_row  = (lane & 7) + ((lane >> 4) << 3);
    const int b_colw = ((lane >> 3) & 1) * 4;
    const uint32_t boff = OFF_B + (uint32_t)(b_row * 20 + b_colw) * 4;

    const uint4* x4 = (const uint4*)g_xh;        // 32 uint4 per x row
    const uint4* w4 = (const uint4*)g_wth;

    // per-thread cp.async assignments: A gets 4 uint4/thread, B 1/thread
    int   rA[4], szA[4];
    size_t srA[4];
    uint32_t dA[4];
    const int qA = tid & 3;
#pragma unroll
    for (int t = 0; t < 4; t++) {
        int i = tid + t * 256;
        rA[t] = i >> 2;
        int gr = row0 + rA[t];
        szA[t] = (gr < N_NODES) ? 16 : 0;
        srA[t] = (size_t)((gr < N_NODES) ? gr : 0) * 32;
        dA[t]  = (uint32_t)(rA[t] * 80 + qA * 16);
    }
    const int rB = tid >> 2, qB = tid & 3;
    const size_t srB = (size_t)(hd * 64 + rB) * 32;
    const uint32_t dB = (uint32_t)(rB * 80 + qB * 16);

#define ISSUE_TILE(st, kit)                                                   \
    do {                                                                      \
        const int kw = (kit) * 4;                                             \
        const uint32_t base = sb + (st) * STAGE;                              \
        CP16(base + OFF_A + dA[0], x4 + srA[0] + kw + qA, szA[0]);            \
        CP16(base + OFF_A + dA[1], x4 + srA[1] + kw + qA, szA[1]);            \
        CP16(base + OFF_A + dA[2], x4 + srA[2] + kw + qA, szA[2]);            \
        CP16(base + OFF_A + dA[3], x4 + srA[3] + kw + qA, szA[3]);            \
        CP16(base + OFF_B + dB,  w4 + srB + kw + qB, 16);                     \
        CP_COMMIT();                                                          \
    } while (0)

    ISSUE_TILE(0, 0);
    ISSUE_TILE(1, 1);

    // single-sync pipeline: wait -> sync -> issue(kit+2) -> compute(kit)
    // safety: top-of-iter sync orders all warps past compute(kit-1), whose
    // stage (kit-1)%3 == (kit+2)%3 is the one being re-issued.
#pragma unroll
    for (int kit = 0; kit < 8; kit++) {
        const int st = kit % 3;
        if (kit < 7) {
            asm volatile("cp.async.wait_group 1;" ::: "memory");
        } else {
            asm volatile("cp.async.wait_group 0;" ::: "memory");
        }
        __syncthreads();
        if (kit + 2 < 8) ISSUE_TILE((kit + 2) % 3, kit + 2);

        const uint32_t sbase = st * STAGE + sb;
#pragma unroll
        for (int kt = 0; kt < 2; kt++) {
            const uint32_t koff = kt * 32;       // 8 words
            uint32_t ar0[4], ar1[4];
            LDSM_X4(ar0, sbase + aoff0 + koff);
            LDSM_X4(ar1, sbase + aoff1 + koff);
#pragma unroll
            for (int q = 0; q < 4; q++) {
                const uint32_t qoff = q * 1280 + koff;   // 16 rows * 80B
                uint32_t br[4];
                LDSM_X4(br, sbase + boff + qoff);
                MMA_F16(acc0[2*q],   ar0[0], ar0[1], ar0[2], ar0[3], br[0], br[1]);
                MMA_F16(acc0[2*q+1], ar0[0], ar0[1], ar0[2], ar0[3], br[2], br[3]);
                MMA_F16(acc1[2*q],   ar1[0], ar1[1], ar1[2], ar1[3], br[0], br[1]);
                MMA_F16(acc1[2*q+1], ar1[0], ar1[1], ar1[2], ar1[3], br[2], br[3]);
            }
        }
    }

    // ---- epilogue: fused attention dots + fp16 h store (two m16 blocks) ----
    const float* ac = a_vec + hd * 2 * OUT_F;
#pragma unroll
    for (int half = 0; half < 2; half++) {
        float (*acc)[4] = half ? acc1 : acc0;
        const int ra = row0 + w * 32 + half * 16 + g;
        float s0 = 0.f, s1 = 0.f, t0 = 0.f, t1 = 0.f;
#pragma unroll
        for (int j = 0; j < 8; j++) {
            int c = j * 8 + 2 * tig;
            float2 as = *(const float2*)(ac + c);
            float2 an = *(const float2*)(ac + OUT_F + c);
            s0 += acc[j][0] * as.x + acc[j][1] * as.y;
            s1 += acc[j][2] * as.x + acc[j][3] * as.y;
            t0 += acc[j][0] * an.x + acc[j][1] * an.y;
            t1 += acc[j][2] * an.x + acc[j][3] * an.y;
        }
#pragma unroll
        for (int o = 1; o < 4; o <<= 1) {
            s0 += __shfl_xor_sync(0xffffffffu, s0, o);
            s1 += __shfl_xor_sync(0xffffffffu, s1, o);
            t0 += __shfl_xor_sync(0xffffffffu, t0, o);
            t1 += __shfl_xor_sync(0xffffffffu, t1, o);
        }
        if (tig == 0) {
            if (ra < N_NODES) {
                g_aself[ra * N_HEADS + hd]  = s0;
                g_aneigh[ra * N_HEADS + hd] = t0;
            }
            if (ra + 8 < N_NODES) {
                g_aself[(ra + 8) * N_HEADS + hd]  = s1;
                g_aneigh[(ra + 8) * N_HEADS + hd] = t1;
            }
        }
        if (ra < N_NODES) {
            __half2* hp = (__half2*)(g_hh + (size_t)ra * HF + hd * OUT_F);
#pragma unroll
            for (int j = 0; j < 8; j++)
                hp[j * 4 + tig] = __floats2half2_rn(acc[j][0], acc[j][1]);
        }
        if (ra + 8 < N_NODES) {
            __half2* hp = (__half2*)(g_hh + (size_t)(ra + 8) * HF + hd * OUT_F);
#pragma unroll
            for (int j = 0; j < 8; j++)
                hp[j * 4 + tig] = __floats2half2_rn(acc[j][2], acc[j][3]);
        }
    }
}

// ---------------- aggregation: one warp per node, ALL 8 heads ----------------
// 2-deep software pipeline: (u,m) fetched 2 ahead, aself 1 ahead.
__global__ void k_agg(float* __restrict__ out) {
    int wid = threadIdx.x >> 5, lane = threadIdx.x & 31;
    int n = blockIdx.x * 8 + wid;
    if (n >= N_NODES) return;

    int s = g_offs[n], e = g_offs[n + 1];
    const uint4* hh4 = (const uint4*)g_hh;          // 64 uint4 per node row
    const int vi = lane * 2;
    const int hsel = lane >> 2;
    const float an = __ldg(&g_aneigh[n * 8 + hsel]);

    float acc[16];
#pragma unroll
    for (int j = 0; j < 16; j++) acc[j] = 0.f;
    float den = 0.f;

    int u0 = 0, u1 = 0;
    float m0 = 0.f, m1 = 0.f, as0 = 0.f;
    if (s < e) {
        u0 = __ldg(&g_csr_src[s]); m0 = __ldg(&g_csr_m[s]);
        as0 = __ldg(&g_aself[u0 * 8 + hsel]);
    }
    if (s + 1 < e) { u1 = __ldg(&g_csr_src[s + 1]); m1 = __ldg(&g_csr_m[s + 1]); }

    for (int i = s; i < e; i++) {
        const int   uc  = u0;
        const float mc  = m0;
        const float asc = as0;
        u0 = u1; m0 = m1;
        if (i + 1 < e) as0 = __ldg(&g_aself[u0 * 8 + hsel]);
        if (i + 2 < e) { u1 = __ldg(&g_csr_src[i + 2]); m1 = __ldg(&g_csr_m[i + 2]); }

        float ev = asc + an;
        ev = (ev > 0.f) ? ev : 0.2f * ev;           // leaky_relu
        float wgt = __expf(ev * mc);
        uint4 v0 = hh4[(size_t)uc * 64 + vi];
        uint4 v1 = hh4[(size_t)uc * 64 + vi + 1];
        den += wgt;
        const __half2* p0 = (const __half2*)&v0;
        const __half2* p1 = (const __half2*)&v1;
#pragma unroll
        for (int j = 0; j < 4; j++) {
            float2 f0 = __half22float2(p0[j]);
            float2 f1 = __half22float2(p1[j]);
            acc[2*j]     = fmaf(wgt, f0.x, acc[2*j]);
            acc[2*j+1]   = fmaf(wgt, f0.y, acc[2*j+1]);
            acc[8+2*j]   = fmaf(wgt, f1.x, acc[8+2*j]);
            acc[8+2*j+1] = fmaf(wgt, f1.y, acc[8+2*j+1]);
        }
    }
    float inv = 1.f / (den + 1e-16f);
    float* op = out + (size_t)n * HF + lane * 16;
#pragma unroll
    for (int j = 0; j < 16; j++) {
        float v = acc[j] * inv;
        acc[j] = (v > 0.f) ? v : expm1f(v);         // elu
    }
#pragma unroll
    for (int j = 0; j < 4; j++)
        *(float4*)(op + j * 4) = make_float4(acc[4*j], acc[4*j+1], acc[4*j+2], acc[4*j+3]);
}

// ---------------- launch: fork CSR chain at t=0 (R12 schedule) ---------------
extern "C" void kernel_launch(void* const* d_in, const int* in_sizes, int n_in,
                              void* d_out, int out_size) {
    const float* x   = (const float*)d_in[0];
    const int*   src = (const int*)d_in[1];
    const int*   dst = (const int*)d_in[2];
    const float* M   = (const float*)d_in[3];
    const float* W   = (const float*)d_in[4];
    const float* a   = (const float*)d_in[5];
    float* out = (float*)d_out;

    static cudaStream_t s2 = nullptr;
    static cudaEvent_t ev_fork = nullptr, ev_join = nullptr;
    if (!s2) {
        cudaStreamCreateWithFlags(&s2, cudaStreamNonBlocking);
        cudaEventCreateWithFlags(&ev_fork, cudaEventDisableTiming);
        cudaEventCreateWithFlags(&ev_join, cudaEventDisableTiming);
        cudaFuncSetAttribute(k_gemm, cudaFuncAttributeMaxDynamicSharedMemorySize,
                             GEMM_SMEM);
    }

    // fork immediately: chain B is independent of the prep/gemm chain
    cudaEventRecord(ev_fork, 0);
    cudaStreamWaitEvent(s2, ev_fork, 0);
    k_zero_deg<<<(N_NODES + 255) / 256, 256, 0, s2>>>();
    k_count<<<(N_EDGES + 255) / 256, 256, 0, s2>>>(dst);
    k_scan<<<1, 1024, 0, s2>>>();
    k_fill<<<(N_EDGES + 255) / 256, 256, 0, s2>>>(src, dst, M);
    cudaEventRecord(ev_join, s2);

    // chain A (stream 0): prep -> gemm
    k_prep<<<(XPAIRS + WELEMS + 255) / 256, 256>>>(x, W);
    k_gemm<<<dim3(N_HEADS, (N_NODES + BM - 1) / BM), 256, GEMM_SMEM>>>(a);

    // join, then aggregate
    cudaStreamWaitEvent(0, ev_join, 0);
    k_agg<<<(N_NODES + 7) / 8, 256>>>(out);
}